// round 2
// baseline (speedup 1.0000x reference)
#include <cuda_runtime.h>
#include <cuda_bf16.h>
#include <math.h>

// Problem constants
constexpr int NN   = 20000;    // nodes
constexpr int INC  = 512;      // input channels
constexpr int C    = 128;      // out channels per head
constexpr int H    = 4;        // heads (layer 1)
constexpr int HID  = H * C;    // 512
constexpr int NE   = 320000;   // edges (without self loops)
constexpr int ET   = NE + NN;  // total edges incl. self loops = 340000
constexpr float NEG_SLOPE = 0.2f;

// ----------------------------------------------------------------------------
// Device-global scratch (no allocation allowed)
// ----------------------------------------------------------------------------
__device__ float g_h1[(size_t)NN * HID];      // x @ W1
__device__ float g_out1[(size_t)NN * HID];    // layer-1 output (post-ELU, input to L2)
__device__ float g_als1[NN * H];
__device__ float g_ald1[NN * H];
__device__ float g_denom1[NN * H];
__device__ float g_w1[(size_t)ET * H];        // per-edge exp weights
__device__ float g_h2[(size_t)NN * C];        // out1 @ W2
__device__ float g_als2[NN];
__device__ float g_ald2[NN];
__device__ float g_denom2[NN];
__device__ float g_w2[ET];
__device__ int   g_src[ET];
__device__ int   g_dst[ET];
__device__ int   g_is64;

// ----------------------------------------------------------------------------
// Edge-index dtype probe + decode.
// Reading the first 320000 int64 words is safe under both layouts
// (320000 * 8 bytes == 640000 * 4 bytes == full int32 buffer size).
// If the buffer is really int32, those int64 reads fuse index pairs and are
// essentially never all inside [0, NN).
// ----------------------------------------------------------------------------
__global__ void det_init_kernel() {
    if (threadIdx.x == 0 && blockIdx.x == 0) g_is64 = 1;
}

__global__ void det_kernel(const long long* __restrict__ p) {
    int i = blockIdx.x * blockDim.x + threadIdx.x;
    for (; i < NE; i += gridDim.x * blockDim.x) {
        unsigned long long v = (unsigned long long)p[i];
        if (v >= (unsigned long long)NN) g_is64 = 0;  // benign race, all write 0
    }
}

__global__ void prep_edges_kernel(const void* __restrict__ eib,
                                  int* __restrict__ src, int* __restrict__ dst) {
    int e = blockIdx.x * blockDim.x + threadIdx.x;
    if (e >= ET) return;
    int s, d;
    if (e < NE) {
        if (g_is64) {
            const long long* p = (const long long*)eib;
            s = (int)p[e]; d = (int)p[NE + e];
        } else {
            const int* p = (const int*)eib;
            s = p[e]; d = p[NE + e];
        }
    } else {
        s = d = e - NE;
    }
    src[e] = s;
    dst[e] = d;
}

// ----------------------------------------------------------------------------
// SGEMM: C[M,N] = A[M,K] * B[K,N], row-major, fp32.
// BM=128, BN=64, BK=16, 256 threads, each computes 8x4.
// ----------------------------------------------------------------------------
#define BM 128
#define BN 64
#define BK 16
#define TM 8
#define TN 4

__global__ __launch_bounds__(256) void sgemm_kernel(
    const float* __restrict__ A, const float* __restrict__ B,
    float* __restrict__ Cc, int M, int N, int K)
{
    __shared__ float As[BK][BM];
    __shared__ float Bs[BK][BN];

    const int tid = threadIdx.x;
    const int rowBase = blockIdx.y * BM;
    const int colBase = blockIdx.x * BN;

    const int aRow = tid >> 2;           // 0..63
    const int aCol = (tid & 3) * 4;      // 0,4,8,12
    const int bRow = tid >> 4;           // 0..15
    const int bCol = (tid & 15) * 4;     // 0..60

    const int tRow = (tid >> 4) * TM;    // 0..120
    const int tCol = (tid & 15) * TN;    // 0..60

    float acc[TM][TN];
#pragma unroll
    for (int i = 0; i < TM; i++)
#pragma unroll
        for (int j = 0; j < TN; j++) acc[i][j] = 0.f;

    for (int k0 = 0; k0 < K; k0 += BK) {
#pragma unroll
        for (int r = 0; r < BM; r += 64) {
            int gr = rowBase + aRow + r;
            float4 v = make_float4(0.f, 0.f, 0.f, 0.f);
            if (gr < M) v = *(const float4*)(A + (size_t)gr * K + k0 + aCol);
            As[aCol + 0][aRow + r] = v.x;
            As[aCol + 1][aRow + r] = v.y;
            As[aCol + 2][aRow + r] = v.z;
            As[aCol + 3][aRow + r] = v.w;
        }
        {
            float4 v = *(const float4*)(B + (size_t)(k0 + bRow) * N + colBase + bCol);
            *(float4*)&Bs[bRow][bCol] = v;
        }
        __syncthreads();

#pragma unroll
        for (int k = 0; k < BK; k++) {
            float ra[TM], rb[TN];
#pragma unroll
            for (int i = 0; i < TM; i++) ra[i] = As[k][tRow + i];
#pragma unroll
            for (int j = 0; j < TN; j++) rb[j] = Bs[k][tCol + j];
#pragma unroll
            for (int i = 0; i < TM; i++)
#pragma unroll
                for (int j = 0; j < TN; j++) acc[i][j] = fmaf(ra[i], rb[j], acc[i][j]);
        }
        __syncthreads();
    }

#pragma unroll
    for (int i = 0; i < TM; i++) {
        int gr = rowBase + tRow + i;
        if (gr < M) {
            float4 v = make_float4(acc[i][0], acc[i][1], acc[i][2], acc[i][3]);
            *(float4*)(Cc + (size_t)gr * N + colBase + tCol) = v;
        }
    }
}

// ----------------------------------------------------------------------------
// Attention coefficients: als[n,h] = <h[n,h,:], a_src[h,:]>, same for ald.
// One block per node, HH warps (one per head).
// ----------------------------------------------------------------------------
template <int HH>
__global__ void attn_kernel(const float* __restrict__ h,
                            const float* __restrict__ a_src,
                            const float* __restrict__ a_dst,
                            float* __restrict__ als, float* __restrict__ ald)
{
    int n = blockIdx.x;
    int warp = threadIdx.x >> 5;
    int lane = threadIdx.x & 31;

    const float4* hp  = (const float4*)(h + (size_t)n * (HH * C) + warp * C);
    const float4* asp = (const float4*)(a_src + warp * C);
    const float4* adp = (const float4*)(a_dst + warp * C);

    float4 v  = hp[lane];
    float4 a1 = asp[lane];
    float4 a2 = adp[lane];
    float ss = v.x * a1.x + v.y * a1.y + v.z * a1.z + v.w * a1.w;
    float sd = v.x * a2.x + v.y * a2.y + v.z * a2.z + v.w * a2.w;

#pragma unroll
    for (int o = 16; o > 0; o >>= 1) {
        ss += __shfl_down_sync(0xffffffffu, ss, o);
        sd += __shfl_down_sync(0xffffffffu, sd, o);
    }
    if (lane == 0) {
        als[n * HH + warp] = ss;
        ald[n * HH + warp] = sd;
    }
}

// ----------------------------------------------------------------------------
// Init kernels
// ----------------------------------------------------------------------------
__global__ void zero_kernel(float* __restrict__ p, int n) {
    int i = blockIdx.x * blockDim.x + threadIdx.x;
    if (i < n) p[i] = 0.f;
}

__global__ void init_bias_kernel(float* __restrict__ p, const float* __restrict__ b,
                                 int n, int cols) {
    int i = blockIdx.x * blockDim.x + threadIdx.x;
    if (i < n) p[i] = b[i % cols];
}

// ----------------------------------------------------------------------------
// Edge weight pass: w[e,h] = exp(leaky_relu(als[src]+ald[dst])); denom[dst,h] += w
// (segment-max shift omitted: mathematically identical softmax; |logits| small)
// ----------------------------------------------------------------------------
template <int HH>
__global__ void edge_w_kernel(const float* __restrict__ als, const float* __restrict__ ald,
                              const int* __restrict__ src, const int* __restrict__ dst,
                              float* __restrict__ w, float* __restrict__ denom)
{
    int e = blockIdx.x * blockDim.x + threadIdx.x;
    if (e >= ET) return;
    int s = src[e], d = dst[e];
#pragma unroll
    for (int hh = 0; hh < HH; hh++) {
        float v = als[s * HH + hh] + ald[d * HH + hh];
        v = v > 0.f ? v : NEG_SLOPE * v;
        float ww = expf(v);
        w[e * HH + hh] = ww;
        atomicAdd(&denom[d * HH + hh], ww);
    }
}

// ----------------------------------------------------------------------------
// Aggregation: out[dst,h,c] += h[src,h,c] * (w[e,h] / (denom[dst,h] + 1e-16))
// One warp per edge, float4 per lane.
// ----------------------------------------------------------------------------
template <int HH>
__global__ void agg_kernel(const float* __restrict__ h, const float* __restrict__ w,
                           const float* __restrict__ denom,
                           const int* __restrict__ src, const int* __restrict__ dst,
                           float* __restrict__ out)
{
    int warp = (blockIdx.x * blockDim.x + threadIdx.x) >> 5;
    if (warp >= ET) return;
    int lane = threadIdx.x & 31;
    int e = warp;
    int s = src[e], d = dst[e];

    constexpr int HC = HH * C;
    float coef[HH];
#pragma unroll
    for (int hh = 0; hh < HH; hh++)
        coef[hh] = w[e * HH + hh] / (denom[d * HH + hh] + 1e-16f);

    const float4* hs = (const float4*)(h + (size_t)s * HC);
    float* od = out + (size_t)d * HC;
#pragma unroll
    for (int i = lane; i < HC / 4; i += 32) {
        float4 v = hs[i];
        float c = coef[i >> 5];   // head = (i*4)/128
        atomicAdd(&od[i * 4 + 0], v.x * c);
        atomicAdd(&od[i * 4 + 1], v.y * c);
        atomicAdd(&od[i * 4 + 2], v.z * c);
        atomicAdd(&od[i * 4 + 3], v.w * c);
    }
}

// ----------------------------------------------------------------------------
// ELU in-place (bias already folded into the init).
// ----------------------------------------------------------------------------
__global__ void elu_kernel(float* __restrict__ x, int n) {
    int i = blockIdx.x * blockDim.x + threadIdx.x;
    if (i < n) {
        float v = x[i];
        x[i] = v > 0.f ? v : expm1f(v);
    }
}

// ----------------------------------------------------------------------------
// Launch
// ----------------------------------------------------------------------------
extern "C" void kernel_launch(void* const* d_in, const int* in_sizes, int n_in,
                              void* d_out, int out_size)
{
    const float* x      = (const float*)d_in[0];
    const void*  ei     = d_in[1];
    const float* W1     = (const float*)d_in[2];
    const float* a_src1 = (const float*)d_in[3];
    const float* a_dst1 = (const float*)d_in[4];
    const float* b1     = (const float*)d_in[5];
    const float* W2     = (const float*)d_in[6];
    const float* a_src2 = (const float*)d_in[7];
    const float* a_dst2 = (const float*)d_in[8];
    const float* b2     = (const float*)d_in[9];
    float*       out    = (float*)d_out;

    float *h1, *out1, *als1, *ald1, *den1, *w1, *h2, *als2, *ald2, *den2, *w2;
    int *src, *dst;
    cudaGetSymbolAddress((void**)&h1,   g_h1);
    cudaGetSymbolAddress((void**)&out1, g_out1);
    cudaGetSymbolAddress((void**)&als1, g_als1);
    cudaGetSymbolAddress((void**)&ald1, g_ald1);
    cudaGetSymbolAddress((void**)&den1, g_denom1);
    cudaGetSymbolAddress((void**)&w1,   g_w1);
    cudaGetSymbolAddress((void**)&h2,   g_h2);
    cudaGetSymbolAddress((void**)&als2, g_als2);
    cudaGetSymbolAddress((void**)&ald2, g_ald2);
    cudaGetSymbolAddress((void**)&den2, g_denom2);
    cudaGetSymbolAddress((void**)&w2,   g_w2);
    cudaGetSymbolAddress((void**)&src,  g_src);
    cudaGetSymbolAddress((void**)&dst,  g_dst);

    // ---------------- Edge index decode ----------------
    det_init_kernel<<<1, 32>>>();
    det_kernel<<<256, 256>>>((const long long*)ei);
    prep_edges_kernel<<<(ET + 255) / 256, 256>>>(ei, src, dst);

    // ---------------- Layer 1 ----------------
    {
        dim3 grid(HID / BN, (NN + BM - 1) / BM);
        sgemm_kernel<<<grid, 256>>>(x, W1, h1, NN, HID, INC);
    }
    attn_kernel<H><<<NN, H * 32>>>(h1, a_src1, a_dst1, als1, ald1);

    zero_kernel<<<(NN * H + 255) / 256, 256>>>(den1, NN * H);
    init_bias_kernel<<<(NN * HID + 255) / 256, 256>>>(out1, b1, NN * HID, HID);

    edge_w_kernel<H><<<(ET + 255) / 256, 256>>>(als1, ald1, src, dst, w1, den1);

    {
        long long threads = (long long)ET * 32;
        agg_kernel<H><<<(int)((threads + 255) / 256), 256>>>(h1, w1, den1, src, dst, out1);
    }
    elu_kernel<<<(NN * HID + 255) / 256, 256>>>(out1, NN * HID);

    // ---------------- Layer 2 ----------------
    {
        dim3 grid(C / BN, (NN + BM - 1) / BM);
        sgemm_kernel<<<grid, 256>>>(out1, W2, h2, NN, C, HID);
    }
    attn_kernel<1><<<NN, 32>>>(h2, a_src2, a_dst2, als2, ald2);

    zero_kernel<<<(NN + 255) / 256, 256>>>(den2, NN);
    init_bias_kernel<<<(NN * C + 255) / 256, 256>>>(out, b2, NN * C, C);

    edge_w_kernel<1><<<(ET + 255) / 256, 256>>>(als2, ald2, src, dst, w2, den2);

    {
        long long threads = (long long)ET * 32;
        agg_kernel<1><<<(int)((threads + 255) / 256), 256>>>(h2, w2, den2, src, dst, out);
    }
}

// round 3
// speedup vs baseline: 1.8883x; 1.8883x over previous
#include <cuda_runtime.h>
#include <cuda_bf16.h>
#include <math.h>

// Problem constants
constexpr int NN   = 20000;    // nodes
constexpr int INC  = 512;      // input channels
constexpr int C    = 128;      // out channels per head
constexpr int H    = 4;        // heads (layer 1)
constexpr int HID  = H * C;    // 512
constexpr int NE   = 320000;   // edges (without self loops)
constexpr int ET   = NE + NN;  // total edges incl. self loops = 340000
constexpr float NEG_SLOPE = 0.2f;

// ----------------------------------------------------------------------------
// Device-global scratch (no allocation allowed)
// ----------------------------------------------------------------------------
__device__ float g_h1[(size_t)NN * HID];      // x @ W1
__device__ float g_out1[(size_t)NN * HID];    // layer-1 output (post-ELU, input to L2)
__device__ float g_als1[NN * H];
__device__ float g_ald1[NN * H];
__device__ float g_h2[(size_t)NN * C];        // out1 @ W2
__device__ float g_als2[NN];
__device__ float g_ald2[NN];
__device__ int   g_src[ET];
__device__ int   g_dst[ET];
__device__ int   g_deg[NN];
__device__ int   g_rowp[NN + 1];
__device__ int   g_cursor[NN];
__device__ int   g_csr_src[ET];
__device__ int   g_is64;

// ----------------------------------------------------------------------------
// f32x2 packed helpers (Blackwell dual-fp32 pipe; ptxas never auto-fuses)
// ----------------------------------------------------------------------------
__device__ __forceinline__ unsigned long long pack_dup(float x) {
    unsigned long long r;
    asm("mov.b64 %0, {%1, %2};" : "=l"(r) : "f"(x), "f"(x));
    return r;
}
__device__ __forceinline__ void ffma2(unsigned long long& d,
                                      unsigned long long a, unsigned long long b) {
    asm("fma.rn.f32x2 %0, %1, %2, %3;" : "=l"(d) : "l"(a), "l"(b), "l"(d));
}
__device__ __forceinline__ float2 unpack2(unsigned long long v) {
    float2 f;
    asm("mov.b64 {%0, %1}, %2;" : "=f"(f.x), "=f"(f.y) : "l"(v));
    return f;
}

// ----------------------------------------------------------------------------
// Edge-index dtype probe + decode (+ degree histogram fused into decode).
// ----------------------------------------------------------------------------
__global__ void det_init_kernel() {
    if (threadIdx.x == 0 && blockIdx.x == 0) g_is64 = 1;
}

__global__ void det_kernel(const long long* __restrict__ p) {
    int i = blockIdx.x * blockDim.x + threadIdx.x;
    for (; i < NE; i += gridDim.x * blockDim.x) {
        unsigned long long v = (unsigned long long)p[i];
        if (v >= (unsigned long long)NN) g_is64 = 0;  // benign race, all write 0
    }
}

__global__ void zero_int_kernel(int* __restrict__ p, int n) {
    int i = blockIdx.x * blockDim.x + threadIdx.x;
    if (i < n) p[i] = 0;
}

__global__ void prep_edges_kernel(const void* __restrict__ eib,
                                  int* __restrict__ src, int* __restrict__ dst,
                                  int* __restrict__ deg) {
    int e = blockIdx.x * blockDim.x + threadIdx.x;
    if (e >= ET) return;
    int s, d;
    if (e < NE) {
        if (g_is64) {
            const long long* p = (const long long*)eib;
            s = (int)p[e]; d = (int)p[NE + e];
        } else {
            const int* p = (const int*)eib;
            s = p[e]; d = p[NE + e];
        }
    } else {
        s = d = e - NE;
    }
    src[e] = s;
    dst[e] = d;
    atomicAdd(&deg[d], 1);
}

// Single-block exclusive scan over NN degree bins; also copies to cursor.
__global__ __launch_bounds__(512) void scan_kernel(const int* __restrict__ deg,
                                                   int* __restrict__ rowp,
                                                   int* __restrict__ cursor) {
    __shared__ int ssum[512];
    const int t = threadIdx.x;
    constexpr int CH = (NN + 511) / 512;   // 40
    int base = t * CH;
    int sum = 0;
#pragma unroll 4
    for (int j = 0; j < CH; j++) {
        int i = base + j;
        if (i < NN) sum += deg[i];
    }
    ssum[t] = sum;
    __syncthreads();
    for (int off = 1; off < 512; off <<= 1) {
        int v = (t >= off) ? ssum[t - off] : 0;
        __syncthreads();
        ssum[t] += v;
        __syncthreads();
    }
    int run = (t == 0) ? 0 : ssum[t - 1];
    for (int j = 0; j < CH; j++) {
        int i = base + j;
        if (i < NN) { rowp[i] = run; cursor[i] = run; run += deg[i]; }
    }
    if (t == 511) rowp[NN] = run;   // == ET
}

__global__ void scatter_kernel(const int* __restrict__ src, const int* __restrict__ dst,
                               int* __restrict__ cursor, int* __restrict__ csr_src) {
    int e = blockIdx.x * blockDim.x + threadIdx.x;
    if (e >= ET) return;
    int p = atomicAdd(&cursor[dst[e]], 1);
    csr_src[p] = src[e];
}

// ----------------------------------------------------------------------------
// SGEMM with packed f32x2 FMAs: C[M,N] = A[M,K] * B[K,N], row-major fp32.
// BM=128, BN=64, BK=16, 256 threads; each thread: 8 rows x 4 cols, rows paired.
// ----------------------------------------------------------------------------
#define BM 128
#define BN 64
#define BK 16
#define TM 8
#define TN 4

__global__ __launch_bounds__(256) void sgemm_kernel(
    const float* __restrict__ A, const float* __restrict__ B,
    float* __restrict__ Cc, int M, int N, int K)
{
    __shared__ float As[BK][BM];
    __shared__ float Bs[BK][BN];

    const int tid = threadIdx.x;
    const int rowBase = blockIdx.y * BM;
    const int colBase = blockIdx.x * BN;

    const int aRow = tid >> 2;           // 0..63
    const int aCol = (tid & 3) * 4;      // 0,4,8,12
    const int bRow = tid >> 4;           // 0..15
    const int bCol = (tid & 15) * 4;     // 0..60

    const int tRow = (tid >> 4) * TM;    // 0..120
    const int tCol = (tid & 15) * TN;    // 0..60

    unsigned long long acc2[TM / 2][TN];
#pragma unroll
    for (int i = 0; i < TM / 2; i++)
#pragma unroll
        for (int j = 0; j < TN; j++) acc2[i][j] = 0ULL;

    for (int k0 = 0; k0 < K; k0 += BK) {
#pragma unroll
        for (int r = 0; r < BM; r += 64) {
            int gr = rowBase + aRow + r;
            float4 v = make_float4(0.f, 0.f, 0.f, 0.f);
            if (gr < M) v = *(const float4*)(A + (size_t)gr * K + k0 + aCol);
            As[aCol + 0][aRow + r] = v.x;
            As[aCol + 1][aRow + r] = v.y;
            As[aCol + 2][aRow + r] = v.z;
            As[aCol + 3][aRow + r] = v.w;
        }
        {
            float4 v = *(const float4*)(B + (size_t)(k0 + bRow) * N + colBase + bCol);
            *(float4*)&Bs[bRow][bCol] = v;
        }
        __syncthreads();

#pragma unroll
        for (int k = 0; k < BK; k++) {
            const ulonglong2* ap = (const ulonglong2*)&As[k][tRow];
            ulonglong2 t0 = ap[0];
            ulonglong2 t1 = ap[1];
            unsigned long long a2[4] = { t0.x, t0.y, t1.x, t1.y };

            float4 bv = *(const float4*)&Bs[k][tCol];
            unsigned long long b2[4] = { pack_dup(bv.x), pack_dup(bv.y),
                                         pack_dup(bv.z), pack_dup(bv.w) };
#pragma unroll
            for (int i = 0; i < TM / 2; i++)
#pragma unroll
                for (int j = 0; j < TN; j++) ffma2(acc2[i][j], a2[i], b2[j]);
        }
        __syncthreads();
    }

#pragma unroll
    for (int i = 0; i < TM / 2; i++) {
        float2 p0 = unpack2(acc2[i][0]);
        float2 p1 = unpack2(acc2[i][1]);
        float2 p2 = unpack2(acc2[i][2]);
        float2 p3 = unpack2(acc2[i][3]);
        int r0 = rowBase + tRow + 2 * i;
        if (r0 < M) {
            float4 v = make_float4(p0.x, p1.x, p2.x, p3.x);
            *(float4*)(Cc + (size_t)r0 * N + colBase + tCol) = v;
        }
        if (r0 + 1 < M) {
            float4 v = make_float4(p0.y, p1.y, p2.y, p3.y);
            *(float4*)(Cc + (size_t)(r0 + 1) * N + colBase + tCol) = v;
        }
    }
}

// ----------------------------------------------------------------------------
// Attention coefficients: als[n,h] = <h[n,h,:], a_src[h,:]>, same for ald.
// ----------------------------------------------------------------------------
template <int HH>
__global__ void attn_kernel(const float* __restrict__ h,
                            const float* __restrict__ a_src,
                            const float* __restrict__ a_dst,
                            float* __restrict__ als, float* __restrict__ ald)
{
    int n = blockIdx.x;
    int warp = threadIdx.x >> 5;
    int lane = threadIdx.x & 31;

    const float4* hp  = (const float4*)(h + (size_t)n * (HH * C) + warp * C);
    const float4* asp = (const float4*)(a_src + warp * C);
    const float4* adp = (const float4*)(a_dst + warp * C);

    float4 v  = hp[lane];
    float4 a1 = asp[lane];
    float4 a2 = adp[lane];
    float ss = v.x * a1.x + v.y * a1.y + v.z * a1.z + v.w * a1.w;
    float sd = v.x * a2.x + v.y * a2.y + v.z * a2.z + v.w * a2.w;

#pragma unroll
    for (int o = 16; o > 0; o >>= 1) {
        ss += __shfl_down_sync(0xffffffffu, ss, o);
        sd += __shfl_down_sync(0xffffffffu, sd, o);
    }
    if (lane == 0) {
        als[n * HH + warp] = ss;
        ald[n * HH + warp] = sd;
    }
}

__device__ __forceinline__ float lrelu(float v) {
    return v > 0.f ? v : NEG_SLOPE * v;
}

// ----------------------------------------------------------------------------
// Fused layer-1 aggregation: block (128 thr) per dst node.
// Phase A: per-head softmax denominator (warp w handles head w).
// Phase B: each thread owns 4 channels; accumulate over in-edges; +bias, ELU.
// ----------------------------------------------------------------------------
__global__ __launch_bounds__(128) void agg1_kernel(
    const float* __restrict__ h, const float* __restrict__ als,
    const float* __restrict__ ald, const float* __restrict__ b1,
    const int* __restrict__ rowp, const int* __restrict__ csr_src,
    float* __restrict__ out)
{
    const int n = blockIdx.x;
    const int tid = threadIdx.x;
    const int lane = tid & 31;
    const int hh = tid >> 5;          // head for this warp / these channels

    __shared__ float s_inv[H];

    const int beg = rowp[n];
    const int end = rowp[n + 1];
    const float aldn = ald[n * H + hh];

    // Phase A: denominator for head hh
    float dsum = 0.f;
    for (int p = beg + lane; p < end; p += 32) {
        int s = csr_src[p];
        dsum += __expf(lrelu(als[s * H + hh] + aldn));
    }
#pragma unroll
    for (int o = 16; o > 0; o >>= 1) dsum += __shfl_xor_sync(0xffffffffu, dsum, o);
    if (lane == 0) s_inv[hh] = 1.f / (dsum + 1e-16f);
    __syncthreads();

    const float inv = s_inv[hh];

    // Phase B: accumulate
    float4 acc = *(const float4*)(b1 + tid * 4);
    const float* hb = h + (size_t)tid * 4;
    for (int p = beg; p < end; p++) {
        int s = csr_src[p];
        float coef = __expf(lrelu(als[s * H + hh] + aldn)) * inv;
        float4 v = *(const float4*)(hb + (size_t)s * HID);
        acc.x = fmaf(v.x, coef, acc.x);
        acc.y = fmaf(v.y, coef, acc.y);
        acc.z = fmaf(v.z, coef, acc.z);
        acc.w = fmaf(v.w, coef, acc.w);
    }

    // ELU epilogue
    acc.x = acc.x > 0.f ? acc.x : expm1f(acc.x);
    acc.y = acc.y > 0.f ? acc.y : expm1f(acc.y);
    acc.z = acc.z > 0.f ? acc.z : expm1f(acc.z);
    acc.w = acc.w > 0.f ? acc.w : expm1f(acc.w);
    *(float4*)(out + (size_t)n * HID + tid * 4) = acc;
}

// ----------------------------------------------------------------------------
// Fused layer-2 aggregation: warp per dst node (4 nodes per block), 1 head.
// ----------------------------------------------------------------------------
__global__ __launch_bounds__(128) void agg2_kernel(
    const float* __restrict__ h, const float* __restrict__ als,
    const float* __restrict__ ald, const float* __restrict__ b2,
    const int* __restrict__ rowp, const int* __restrict__ csr_src,
    float* __restrict__ out)
{
    const int n = blockIdx.x * 4 + (threadIdx.x >> 5);
    if (n >= NN) return;
    const int lane = threadIdx.x & 31;

    const int beg = rowp[n];
    const int end = rowp[n + 1];
    const float aldn = ald[n];

    float dsum = 0.f;
    for (int p = beg + lane; p < end; p += 32) {
        int s = csr_src[p];
        dsum += __expf(lrelu(als[s] + aldn));
    }
#pragma unroll
    for (int o = 16; o > 0; o >>= 1) dsum += __shfl_xor_sync(0xffffffffu, dsum, o);
    const float inv = 1.f / (dsum + 1e-16f);

    float4 acc = *(const float4*)(b2 + lane * 4);
    const float* hb = h + (size_t)lane * 4;
    for (int p = beg; p < end; p++) {
        int s = csr_src[p];
        float coef = __expf(lrelu(als[s] + aldn)) * inv;
        float4 v = *(const float4*)(hb + (size_t)s * C);
        acc.x = fmaf(v.x, coef, acc.x);
        acc.y = fmaf(v.y, coef, acc.y);
        acc.z = fmaf(v.z, coef, acc.z);
        acc.w = fmaf(v.w, coef, acc.w);
    }
    *(float4*)(out + (size_t)n * C + lane * 4) = acc;
}

// ----------------------------------------------------------------------------
// Launch
// ----------------------------------------------------------------------------
extern "C" void kernel_launch(void* const* d_in, const int* in_sizes, int n_in,
                              void* d_out, int out_size)
{
    const float* x      = (const float*)d_in[0];
    const void*  ei     = d_in[1];
    const float* W1     = (const float*)d_in[2];
    const float* a_src1 = (const float*)d_in[3];
    const float* a_dst1 = (const float*)d_in[4];
    const float* b1     = (const float*)d_in[5];
    const float* W2     = (const float*)d_in[6];
    const float* a_src2 = (const float*)d_in[7];
    const float* a_dst2 = (const float*)d_in[8];
    const float* b2     = (const float*)d_in[9];
    float*       out    = (float*)d_out;

    float *h1, *out1, *als1, *ald1, *h2, *als2, *ald2;
    int *src, *dst, *deg, *rowp, *cursor, *csr_src;
    cudaGetSymbolAddress((void**)&h1,      g_h1);
    cudaGetSymbolAddress((void**)&out1,    g_out1);
    cudaGetSymbolAddress((void**)&als1,    g_als1);
    cudaGetSymbolAddress((void**)&ald1,    g_ald1);
    cudaGetSymbolAddress((void**)&h2,      g_h2);
    cudaGetSymbolAddress((void**)&als2,    g_als2);
    cudaGetSymbolAddress((void**)&ald2,    g_ald2);
    cudaGetSymbolAddress((void**)&src,     g_src);
    cudaGetSymbolAddress((void**)&dst,     g_dst);
    cudaGetSymbolAddress((void**)&deg,     g_deg);
    cudaGetSymbolAddress((void**)&rowp,    g_rowp);
    cudaGetSymbolAddress((void**)&cursor,  g_cursor);
    cudaGetSymbolAddress((void**)&csr_src, g_csr_src);

    // ---------------- Edge decode + CSR build ----------------
    det_init_kernel<<<1, 32>>>();
    zero_int_kernel<<<(NN + 255) / 256, 256>>>(deg, NN);
    det_kernel<<<256, 256>>>((const long long*)ei);
    prep_edges_kernel<<<(ET + 255) / 256, 256>>>(ei, src, dst, deg);
    scan_kernel<<<1, 512>>>(deg, rowp, cursor);
    scatter_kernel<<<(ET + 255) / 256, 256>>>(src, dst, cursor, csr_src);

    // ---------------- Layer 1 ----------------
    {
        dim3 grid(HID / BN, (NN + BM - 1) / BM);
        sgemm_kernel<<<grid, 256>>>(x, W1, h1, NN, HID, INC);
    }
    attn_kernel<H><<<NN, H * 32>>>(h1, a_src1, a_dst1, als1, ald1);
    agg1_kernel<<<NN, 128>>>(h1, als1, ald1, b1, rowp, csr_src, out1);

    // ---------------- Layer 2 ----------------
    {
        dim3 grid(C / BN, (NN + BM - 1) / BM);
        sgemm_kernel<<<grid, 256>>>(out1, W2, h2, NN, C, HID);
    }
    attn_kernel<1><<<NN, 32>>>(h2, a_src2, a_dst2, als2, ald2);
    agg2_kernel<<<(NN + 3) / 4, 128>>>(h2, als2, ald2, b2, rowp, csr_src, out);
}

// round 5
// speedup vs baseline: 2.4765x; 1.3115x over previous
#include <cuda_runtime.h>
#include <cuda_bf16.h>
#include <math.h>
#include <stdint.h>

// Problem constants
constexpr int NN   = 20000;
constexpr int INC  = 512;
constexpr int C    = 128;
constexpr int H    = 4;
constexpr int HID  = H * C;        // 512
constexpr int NE   = 320000;
constexpr int ET   = NE + NN;      // 340000
constexpr int K2   = 3 * 512;      // widened K for bf16 split GEMM
constexpr float NEG_SLOPE = 0.2f;

// ----------------------------------------------------------------------------
// Device-global scratch
// ----------------------------------------------------------------------------
__device__ __nv_bfloat16 g_xs[(size_t)NN * K2];     // split(x)        [N,1536]
__device__ __nv_bfloat16 g_w1t[(size_t)HID * K2];   // split(W1^T)     [512,1536]
__device__ __nv_bfloat16 g_w2t[(size_t)C * K2];     // split(W2^T)     [128,1536]
__device__ float g_h1[(size_t)NN * HID];            // x @ W1
__device__ __nv_bfloat16 g_out1s[(size_t)NN * K2];  // split(elu(agg1)) [N,1536]
__device__ float g_h2[(size_t)NN * C];              // out1 @ W2
__device__ float g_als1[NN * H];
__device__ float g_ald1[NN * H];
__device__ float g_als2[NN];
__device__ float g_ald2[NN];
__device__ int   g_src[ET];
__device__ int   g_dst[ET];
__device__ int   g_deg[NN];
__device__ int   g_rowp[NN + 1];
__device__ int   g_cursor[NN];
__device__ int   g_csr_src[ET];
__device__ int   g_is64;

// ----------------------------------------------------------------------------
// Edge-index dtype probe + decode + CSR build
// ----------------------------------------------------------------------------
__global__ void det_init_kernel() {
    if (threadIdx.x == 0 && blockIdx.x == 0) g_is64 = 1;
}
__global__ void det_kernel(const long long* __restrict__ p) {
    int i = blockIdx.x * blockDim.x + threadIdx.x;
    for (; i < NE; i += gridDim.x * blockDim.x) {
        unsigned long long v = (unsigned long long)p[i];
        if (v >= (unsigned long long)NN) g_is64 = 0;
    }
}
__global__ void zero_int_kernel(int* __restrict__ p, int n) {
    int i = blockIdx.x * blockDim.x + threadIdx.x;
    if (i < n) p[i] = 0;
}
__global__ void prep_edges_kernel(const void* __restrict__ eib,
                                  int* __restrict__ src, int* __restrict__ dst,
                                  int* __restrict__ deg) {
    int e = blockIdx.x * blockDim.x + threadIdx.x;
    if (e >= ET) return;
    int s, d;
    if (e < NE) {
        if (g_is64) {
            const long long* p = (const long long*)eib;
            s = (int)p[e]; d = (int)p[NE + e];
        } else {
            const int* p = (const int*)eib;
            s = p[e]; d = p[NE + e];
        }
    } else {
        s = d = e - NE;
    }
    src[e] = s; dst[e] = d;
    atomicAdd(&deg[d], 1);
}
__global__ __launch_bounds__(512) void scan_kernel(const int* __restrict__ deg,
                                                   int* __restrict__ rowp,
                                                   int* __restrict__ cursor) {
    __shared__ int ssum[512];
    const int t = threadIdx.x;
    constexpr int CH = (NN + 511) / 512;
    int base = t * CH;
    int sum = 0;
    for (int j = 0; j < CH; j++) { int i = base + j; if (i < NN) sum += deg[i]; }
    ssum[t] = sum;
    __syncthreads();
    for (int off = 1; off < 512; off <<= 1) {
        int v = (t >= off) ? ssum[t - off] : 0;
        __syncthreads();
        ssum[t] += v;
        __syncthreads();
    }
    int run = (t == 0) ? 0 : ssum[t - 1];
    for (int j = 0; j < CH; j++) {
        int i = base + j;
        if (i < NN) { rowp[i] = run; cursor[i] = run; run += deg[i]; }
    }
    if (t == 511) rowp[NN] = run;
}
__global__ void scatter_kernel(const int* __restrict__ src, const int* __restrict__ dst,
                               int* __restrict__ cursor, int* __restrict__ csr_src) {
    int e = blockIdx.x * blockDim.x + threadIdx.x;
    if (e >= ET) return;
    int p = atomicAdd(&cursor[dst[e]], 1);
    csr_src[p] = src[e];
}

// ----------------------------------------------------------------------------
// fp32 -> bf16 hi/lo split conversions.
// A-side rows: [0,512)=hi, [512,1024)=hi, [1024,1536)=lo
// B-side rows: [0,512)=hi, [512,1024)=lo, [1024,1536)=hi
// => A@B over K' = Ahi*Bhi + Ahi*Blo + Alo*Bhi  (drops only ~2^-18 lo*lo term)
// ----------------------------------------------------------------------------
__global__ void conv_x_kernel(const float* __restrict__ x, __nv_bfloat16* __restrict__ xs) {
    int idx = blockIdx.x * blockDim.x + threadIdx.x;
    if (idx >= NN * 128) return;
    int row = idx >> 7, q = idx & 127;
    float4 v = *(const float4*)(x + (size_t)row * 512 + q * 4);
    __nv_bfloat16* o = xs + (size_t)row * K2 + q * 4;
    float vals[4] = { v.x, v.y, v.z, v.w };
#pragma unroll
    for (int j = 0; j < 4; j++) {
        __nv_bfloat16 hi = __float2bfloat16(vals[j]);
        __nv_bfloat16 lo = __float2bfloat16(vals[j] - __bfloat162float(hi));
        o[j] = hi; o[512 + j] = hi; o[1024 + j] = lo;
    }
}

// W [K=512, N] row-major -> wt [N, K2] (B-side layout), transposed.
__global__ void conv_w_kernel(const float* __restrict__ W, __nv_bfloat16* __restrict__ wt, int N) {
    int idx = blockIdx.x * blockDim.x + threadIdx.x;
    if (idx >= 512 * N) return;
    int k = idx / N, n = idx % N;
    float v = W[(size_t)k * N + n];
    __nv_bfloat16 hi = __float2bfloat16(v);
    __nv_bfloat16 lo = __float2bfloat16(v - __bfloat162float(hi));
    __nv_bfloat16* o = wt + (size_t)n * K2;
    o[k] = hi; o[512 + k] = lo; o[1024 + k] = hi;
}

// ----------------------------------------------------------------------------
// HMMA (mma.sync bf16) GEMM: Cm[M,Ntot](fp32) = A[M,K2] @ B[Ntot,K2]^T
// CTA tile 128x128, 256 threads (8 warps, 2x4 grid, warp tile 64x32).
// BK=32, double-buffered cp.async, padded SMEM stride 40 bf16 (80 B).
// ----------------------------------------------------------------------------
constexpr int GK  = 32;                 // BK
constexpr int LDT = 40;                 // padded SMEM stride in bf16 (80 B)
constexpr int TSZ = 128 * LDT * 2;      // one A or B tile: 10240 B
constexpr int NCH = K2 / GK;            // 48

__device__ __forceinline__ uint32_t smem_u32(const void* p) {
    uint32_t a;
    asm("{ .reg .u64 t; cvta.to.shared.u64 t, %1; cvt.u32.u64 %0, t; }"
        : "=r"(a) : "l"(p));
    return a;
}
__device__ __forceinline__ void cp16(uint32_t dst, const void* src, uint32_t sz) {
    asm volatile("cp.async.ca.shared.global [%0], [%1], 16, %2;"
                 :: "r"(dst), "l"(src), "r"(sz));
}
__device__ __forceinline__ void cp_commit() {
    asm volatile("cp.async.commit_group;");
}
__device__ __forceinline__ void ldm_x4(uint32_t* r, uint32_t addr) {
    asm volatile("ldmatrix.sync.aligned.m8n8.x4.shared.b16 {%0,%1,%2,%3}, [%4];"
                 : "=r"(r[0]), "=r"(r[1]), "=r"(r[2]), "=r"(r[3]) : "r"(addr));
}
__device__ __forceinline__ void mma16816(float* d, const uint32_t* a, const uint32_t* b) {
    asm volatile(
        "mma.sync.aligned.m16n8k16.row.col.f32.bf16.bf16.f32 "
        "{%0,%1,%2,%3}, {%4,%5,%6,%7}, {%8,%9}, {%0,%1,%2,%3};"
        : "+f"(d[0]), "+f"(d[1]), "+f"(d[2]), "+f"(d[3])
        : "r"(a[0]), "r"(a[1]), "r"(a[2]), "r"(a[3]), "r"(b[0]), "r"(b[1]));
}

__global__ __launch_bounds__(256, 2) void hmma_gemm_kernel(
    const __nv_bfloat16* __restrict__ A, const __nv_bfloat16* __restrict__ B,
    float* __restrict__ Cm, int M, int Ntot)
{
    __shared__ __align__(128) char smem[2 * 2 * TSZ];
    const uint32_t sbase = smem_u32(smem);

    const int tid  = threadIdx.x;
    const int wid  = tid >> 5;
    const int lane = tid & 31;
    const int warp_m = (wid >> 2) * 64;
    const int warp_n = (wid & 3) * 32;
    const int rowBase = blockIdx.y * 128;
    const int colBase = blockIdx.x * 128;

    // global-load assignment: 16B chunk ids {tid, tid+256}; row = id>>2, c16 = id&3
    const int r0 = tid >> 2,          c0 = tid & 3;
    const int r1 = (tid + 256) >> 2,  c1 = (tid + 256) & 3;

    float acc[4][4][4];
#pragma unroll
    for (int i = 0; i < 4; i++)
#pragma unroll
        for (int j = 0; j < 4; j++)
#pragma unroll
            for (int q = 0; q < 4; q++) acc[i][j][q] = 0.f;

    auto prefetch = [&](int ch, int buf) {
        uint32_t ab = sbase + buf * 2 * TSZ;
        uint32_t bb = ab + TSZ;
        const __nv_bfloat16* Ac = A + (size_t)0 * K2 + ch * GK;
        const __nv_bfloat16* Bc = B + ch * GK;
        // A rows may be OOB -> zero-fill
        cp16(ab + r0 * (LDT * 2) + c0 * 16,
             Ac + (size_t)(rowBase + r0) * K2 + c0 * 8,
             (rowBase + r0 < M) ? 16u : 0u);
        cp16(ab + r1 * (LDT * 2) + c1 * 16,
             Ac + (size_t)(rowBase + r1) * K2 + c1 * 8,
             (rowBase + r1 < M) ? 16u : 0u);
        // B always in-bounds (Ntot multiple of 128)
        cp16(bb + r0 * (LDT * 2) + c0 * 16,
             Bc + (size_t)(colBase + r0) * K2 + c0 * 8, 16u);
        cp16(bb + r1 * (LDT * 2) + c1 * 16,
             Bc + (size_t)(colBase + r1) * K2 + c1 * 8, 16u);
        cp_commit();
    };

    prefetch(0, 0);

    for (int ch = 0; ch < NCH; ch++) {
        const int buf = ch & 1;
        if (ch + 1 < NCH) {
            prefetch(ch + 1, buf ^ 1);
            asm volatile("cp.async.wait_group 1;");
        } else {
            asm volatile("cp.async.wait_group 0;");
        }
        __syncthreads();

        uint32_t ab = sbase + buf * 2 * TSZ;
        uint32_t bb = ab + TSZ;

#pragma unroll
        for (int ks = 0; ks < 2; ks++) {
            uint32_t afrag[4][4];
#pragma unroll
            for (int i = 0; i < 4; i++) {
                int row = warp_m + i * 16 + (lane & 15);
                int col = ks * 16 + ((lane >> 4) << 3);
                ldm_x4(afrag[i], ab + row * (LDT * 2) + col * 2);
            }
            uint32_t bfrag[4][2];
#pragma unroll
            for (int jj = 0; jj < 2; jj++) {
                uint32_t r[4];
                int nrow = warp_n + jj * 16 + (lane & 7) + ((lane >> 4) << 3);
                int col  = ks * 16 + (((lane >> 3) & 1) << 3);
                ldm_x4(r, bb + nrow * (LDT * 2) + col * 2);
                bfrag[2 * jj + 0][0] = r[0]; bfrag[2 * jj + 0][1] = r[1];
                bfrag[2 * jj + 1][0] = r[2]; bfrag[2 * jj + 1][1] = r[3];
            }
#pragma unroll
            for (int i = 0; i < 4; i++)
#pragma unroll
                for (int j = 0; j < 4; j++)
                    mma16816(acc[i][j], afrag[i], bfrag[j]);
        }
        __syncthreads();
    }

    // Epilogue
#pragma unroll
    for (int i = 0; i < 4; i++) {
        int rr = rowBase + warp_m + i * 16 + (lane >> 2);
#pragma unroll
        for (int j = 0; j < 4; j++) {
            int cc = colBase + warp_n + j * 8 + (lane & 3) * 2;
            if (rr < M)
                *(float2*)(Cm + (size_t)rr * Ntot + cc) = make_float2(acc[i][j][0], acc[i][j][1]);
            if (rr + 8 < M)
                *(float2*)(Cm + (size_t)(rr + 8) * Ntot + cc) = make_float2(acc[i][j][2], acc[i][j][3]);
        }
    }
}

// ----------------------------------------------------------------------------
// Attention coefficients
// ----------------------------------------------------------------------------
template <int HH>
__global__ void attn_kernel(const float* __restrict__ h,
                            const float* __restrict__ a_src,
                            const float* __restrict__ a_dst,
                            float* __restrict__ als, float* __restrict__ ald)
{
    int n = blockIdx.x;
    int warp = threadIdx.x >> 5;
    int lane = threadIdx.x & 31;

    const float4* hp  = (const float4*)(h + (size_t)n * (HH * C) + warp * C);
    const float4* asp = (const float4*)(a_src + warp * C);
    const float4* adp = (const float4*)(a_dst + warp * C);

    float4 v  = hp[lane];
    float4 a1 = asp[lane];
    float4 a2 = adp[lane];
    float ss = v.x * a1.x + v.y * a1.y + v.z * a1.z + v.w * a1.w;
    float sd = v.x * a2.x + v.y * a2.y + v.z * a2.z + v.w * a2.w;

#pragma unroll
    for (int o = 16; o > 0; o >>= 1) {
        ss += __shfl_down_sync(0xffffffffu, ss, o);
        sd += __shfl_down_sync(0xffffffffu, sd, o);
    }
    if (lane == 0) {
        als[n * HH + warp] = ss;
        ald[n * HH + warp] = sd;
    }
}

__device__ __forceinline__ float lrelu(float v) {
    return v > 0.f ? v : NEG_SLOPE * v;
}

// ----------------------------------------------------------------------------
// Fused layer-1 aggregation + ELU + bf16 split output (A-side layout for GEMM2).
// ----------------------------------------------------------------------------
__global__ __launch_bounds__(128) void agg1_kernel(
    const float* __restrict__ h, const float* __restrict__ als,
    const float* __restrict__ ald, const float* __restrict__ b1,
    const int* __restrict__ rowp, const int* __restrict__ csr_src,
    __nv_bfloat16* __restrict__ outs)
{
    const int n = blockIdx.x;
    const int tid = threadIdx.x;
    const int lane = tid & 31;
    const int hh = tid >> 5;

    __shared__ float s_inv[H];

    const int beg = rowp[n];
    const int end = rowp[n + 1];
    const float aldn = ald[n * H + hh];

    float dsum = 0.f;
    for (int p = beg + lane; p < end; p += 32) {
        int s = csr_src[p];
        dsum += __expf(lrelu(als[s * H + hh] + aldn));
    }
#pragma unroll
    for (int o = 16; o > 0; o >>= 1) dsum += __shfl_xor_sync(0xffffffffu, dsum, o);
    if (lane == 0) s_inv[hh] = 1.f / (dsum + 1e-16f);
    __syncthreads();

    const float inv = s_inv[hh];

    float4 acc = *(const float4*)(b1 + tid * 4);
    const float* hb = h + (size_t)tid * 4;
    for (int p = beg; p < end; p++) {
        int s = csr_src[p];
        float coef = __expf(lrelu(als[s * H + hh] + aldn)) * inv;
        float4 v = *(const float4*)(hb + (size_t)s * HID);
        acc.x = fmaf(v.x, coef, acc.x);
        acc.y = fmaf(v.y, coef, acc.y);
        acc.z = fmaf(v.z, coef, acc.z);
        acc.w = fmaf(v.w, coef, acc.w);
    }

    float vals[4] = { acc.x, acc.y, acc.z, acc.w };
    __nv_bfloat16* orow = outs + (size_t)n * K2;
#pragma unroll
    for (int j = 0; j < 4; j++) {
        float v = vals[j];
        v = v > 0.f ? v : expm1f(v);
        __nv_bfloat16 hi = __float2bfloat16(v);
        __nv_bfloat16 lo = __float2bfloat16(v - __bfloat162float(hi));
        int c = tid * 4 + j;
        orow[c] = hi; orow[512 + c] = hi; orow[1024 + c] = lo;
    }
}

// ----------------------------------------------------------------------------
// Fused layer-2 aggregation: warp per dst node.
// ----------------------------------------------------------------------------
__global__ __launch_bounds__(128) void agg2_kernel(
    const float* __restrict__ h, const float* __restrict__ als,
    const float* __restrict__ ald, const float* __restrict__ b2,
    const int* __restrict__ rowp, const int* __restrict__ csr_src,
    float* __restrict__ out)
{
    const int n = blockIdx.x * 4 + (threadIdx.x >> 5);
    if (n >= NN) return;
    const int lane = threadIdx.x & 31;

    const int beg = rowp[n];
    const int end = rowp[n + 1];
    const float aldn = ald[n];

    float dsum = 0.f;
    for (int p = beg + lane; p < end; p += 32) {
        int s = csr_src[p];
        dsum += __expf(lrelu(als[s] + aldn));
    }
#pragma unroll
    for (int o = 16; o > 0; o >>= 1) dsum += __shfl_xor_sync(0xffffffffu, dsum, o);
    const float inv = 1.f / (dsum + 1e-16f);

    float4 acc = *(const float4*)(b2 + lane * 4);
    const float* hb = h + (size_t)lane * 4;
    for (int p = beg; p < end; p++) {
        int s = csr_src[p];
        float coef = __expf(lrelu(als[s] + aldn)) * inv;
        float4 v = *(const float4*)(hb + (size_t)s * C);
        acc.x = fmaf(v.x, coef, acc.x);
        acc.y = fmaf(v.y, coef, acc.y);
        acc.z = fmaf(v.z, coef, acc.z);
        acc.w = fmaf(v.w, coef, acc.w);
    }
    *(float4*)(out + (size_t)n * C + lane * 4) = acc;
}

// ----------------------------------------------------------------------------
// Launch
// ----------------------------------------------------------------------------
extern "C" void kernel_launch(void* const* d_in, const int* in_sizes, int n_in,
                              void* d_out, int out_size)
{
    const float* x      = (const float*)d_in[0];
    const void*  ei     = d_in[1];
    const float* W1     = (const float*)d_in[2];
    const float* a_src1 = (const float*)d_in[3];
    const float* a_dst1 = (const float*)d_in[4];
    const float* b1     = (const float*)d_in[5];
    const float* W2     = (const float*)d_in[6];
    const float* a_src2 = (const float*)d_in[7];
    const float* a_dst2 = (const float*)d_in[8];
    const float* b2     = (const float*)d_in[9];
    float*       out    = (float*)d_out;

    __nv_bfloat16 *xs, *w1t, *w2t, *out1s;
    float *h1, *h2, *als1, *ald1, *als2, *ald2;
    int *src, *dst, *deg, *rowp, *cursor, *csr_src;
    cudaGetSymbolAddress((void**)&xs,      g_xs);
    cudaGetSymbolAddress((void**)&w1t,     g_w1t);
    cudaGetSymbolAddress((void**)&w2t,     g_w2t);
    cudaGetSymbolAddress((void**)&out1s,   g_out1s);
    cudaGetSymbolAddress((void**)&h1,      g_h1);
    cudaGetSymbolAddress((void**)&h2,      g_h2);
    cudaGetSymbolAddress((void**)&als1,    g_als1);
    cudaGetSymbolAddress((void**)&ald1,    g_ald1);
    cudaGetSymbolAddress((void**)&als2,    g_als2);
    cudaGetSymbolAddress((void**)&ald2,    g_ald2);
    cudaGetSymbolAddress((void**)&src,     g_src);
    cudaGetSymbolAddress((void**)&dst,     g_dst);
    cudaGetSymbolAddress((void**)&deg,     g_deg);
    cudaGetSymbolAddress((void**)&rowp,    g_rowp);
    cudaGetSymbolAddress((void**)&cursor,  g_cursor);
    cudaGetSymbolAddress((void**)&csr_src, g_csr_src);

    // ---------------- Edge decode + CSR build ----------------
    det_init_kernel<<<1, 32>>>();
    zero_int_kernel<<<(NN + 255) / 256, 256>>>(deg, NN);
    det_kernel<<<256, 256>>>((const long long*)ei);
    prep_edges_kernel<<<(ET + 255) / 256, 256>>>(ei, src, dst, deg);
    scan_kernel<<<1, 512>>>(deg, rowp, cursor);
    scatter_kernel<<<(ET + 255) / 256, 256>>>(src, dst, cursor, csr_src);

    // ---------------- Conversions ----------------
    conv_x_kernel<<<(NN * 128 + 255) / 256, 256>>>(x, xs);
    conv_w_kernel<<<(512 * HID + 255) / 256, 256>>>(W1, w1t, HID);
    conv_w_kernel<<<(512 * C + 255) / 256, 256>>>(W2, w2t, C);

    // ---------------- Layer 1 ----------------
    {
        dim3 grid(HID / 128, (NN + 127) / 128);   // (4, 157)
        hmma_gemm_kernel<<<grid, 256>>>(xs, w1t, h1, NN, HID);
    }
    attn_kernel<H><<<NN, H * 32>>>(h1, a_src1, a_dst1, als1, ald1);
    agg1_kernel<<<NN, 128>>>(h1, als1, ald1, b1, rowp, csr_src, out1s);

    // ---------------- Layer 2 ----------------
    {
        dim3 grid(1, (NN + 127) / 128);           // (1, 157)
        hmma_gemm_kernel<<<grid, 256>>>(out1s, w2t, h2, NN, C);
    }
    attn_kernel<1><<<NN, 32>>>(h2, a_src2, a_dst2, als2, ald2);
    agg2_kernel<<<(NN + 3) / 4, 128>>>(h2, als2, ald2, b2, rowp, csr_src, out);
}